// round 1
// baseline (speedup 1.0000x reference)
#include <cuda_runtime.h>

// ModelFilter: y = gain * clip(IIR2(FIR2(x)), -1, 1)
// Batched biquad via chunked parallel-scan decomposition of the order-2
// linear recurrence.
//
//   B = 64 rows, T = 262144 samples, L = 256 chunk, C = 1024 chunks/row.
//   Phase 1: per-chunk zero-IC recurrence -> end states d_c
//   Phase 2: per-row Kogge-Stone scan e_c = A e_{c-1} + d_c, A = M^L (fp64 setup)
//   Phase 3: per-chunk recurrence from true initial state, clip*gain, write out.

#define BATCH 64
#define TLEN  262144
#define CHUNK 256
#define CPR   (TLEN / CHUNK)          // 1024 chunks per row
#define TOTAL_CHUNKS (BATCH * CPR)    // 65536
#define CPB   128                     // chunks per block in phase 1/3
#define NBLK  (TOTAL_CHUNKS / CPB)    // 512 blocks
#define WIN   32                      // samples per staged window
#define NW    (CHUNK / WIN)           // 8 windows per chunk
#define PAD   33                      // shared stride (bank-conflict-free)

// Scratch (static __device__ -- no allocations allowed)
__device__ float2 g_d[TOTAL_CHUNKS];     // phase-1 zero-IC end states
__device__ float2 g_init[TOTAL_CHUNKS];  // phase-2 true initial states
__device__ float  g_cf[6];               // a1, a2, b0, b1, b2, gain
__device__ float4 g_P[10];               // A^(2^k), k = 0..9 (2x2 row-major)

// ---------------------------------------------------------------------------
__global__ void setup_kernel(const float* __restrict__ a,
                             const float* __restrict__ b,
                             const float* __restrict__ gain)
{
    double a0  = (double)a[0];
    double inv = 1.0 / a0;
    double a1 = (double)a[1] * inv;
    double a2 = (double)a[2] * inv;
    g_cf[0] = (float)a1;
    g_cf[1] = (float)a2;
    g_cf[2] = (float)((double)b[0] * inv);
    g_cf[3] = (float)((double)b[1] * inv);
    g_cf[4] = (float)((double)b[2] * inv);
    g_cf[5] = gain[0];

    // M = [[-a1, -a2], [1, 0]];  A = M^CHUNK (CHUNK = 2^8 -> 8 squarings)
    double m00 = -a1, m01 = -a2, m10 = 1.0, m11 = 0.0;
    #pragma unroll
    for (int i = 0; i < 8; i++) {
        double t00 = m00 * m00 + m01 * m10;
        double t01 = m00 * m01 + m01 * m11;
        double t10 = m10 * m00 + m11 * m10;
        double t11 = m10 * m01 + m11 * m11;
        m00 = t00; m01 = t01; m10 = t10; m11 = t11;
    }
    #pragma unroll
    for (int k = 0; k < 10; k++) {
        g_P[k] = make_float4((float)m00, (float)m01, (float)m10, (float)m11);
        double t00 = m00 * m00 + m01 * m10;
        double t01 = m00 * m01 + m01 * m11;
        double t10 = m10 * m00 + m11 * m10;
        double t11 = m10 * m01 + m11 * m11;
        m00 = t00; m01 = t01; m10 = t10; m11 = t11;
    }
}

// ---------------------------------------------------------------------------
// Phase 1: zero-IC chunk recurrence -> end states.
__global__ void __launch_bounds__(CPB)
phase1_kernel(const float* __restrict__ x)
{
    __shared__ float sx[CPB * PAD];

    const int t  = threadIdx.x;
    const int bg = blockIdx.x * CPB;       // first global chunk of this block
    const int g  = bg + t;
    const int row = bg >> 10;              // CPB divides CPR -> one row/block
    const int bc  = bg & (CPR - 1);        // first chunk-in-row of this block
    const int cir = bc + t;                // this thread's chunk-in-row

    const float a1 = g_cf[0], a2 = g_cf[1];
    const float b0 = g_cf[2], b1 = g_cf[3], b2 = g_cf[4];

    const float* xr = x + (size_t)row * TLEN;
    const float4* xb4 =
        (const float4*)(xr + (size_t)bc * CHUNK);

    // True x history at chunk entry (zero only at row start)
    float x1 = 0.0f, x2 = 0.0f;
    if (cir > 0) {
        int n0 = cir * CHUNK;
        x1 = xr[n0 - 1];
        x2 = xr[n0 - 2];
    }

    float y1 = 0.0f, y2 = 0.0f;

    for (int w = 0; w < NW; w++) {
        // Cooperative coalesced load of this window (CPB chunks x WIN samples)
        #pragma unroll
        for (int j = 0; j < (CPB * WIN / 4) / CPB; j++) {   // 8 float4/thread
            int idx = t + CPB * j;
            int c   = idx >> 3;
            int off = idx & 7;
            float4 v = xb4[c * (CHUNK / 4) + w * (WIN / 4) + off];
            float* s = &sx[c * PAD + off * 4];
            s[0] = v.x; s[1] = v.y; s[2] = v.z; s[3] = v.w;
        }
        __syncthreads();

        #pragma unroll
        for (int i = 0; i < WIN; i++) {
            float xn = sx[t * PAD + i];
            float f  = fmaf(b2, x2, fmaf(b1, x1, b0 * xn));
            float y  = fmaf(-a2, y2, fmaf(-a1, y1, f));
            x2 = x1; x1 = xn;
            y2 = y1; y1 = y;
        }
        __syncthreads();
    }

    g_d[g] = make_float2(y1, y2);
}

// ---------------------------------------------------------------------------
// Phase 2: per-row Kogge-Stone scan over chunk states.
__global__ void __launch_bounds__(CPR)
phase2_kernel()
{
    __shared__ float2 s[CPR];
    const int c   = threadIdx.x;
    const int row = blockIdx.x;

    s[c] = g_d[row * CPR + c];
    __syncthreads();

    #pragma unroll
    for (int k = 0; k < 10; k++) {
        const int o = 1 << k;
        float4 P = g_P[k];
        float2 v = s[c];
        float2 u = (c >= o) ? s[c - o] : make_float2(0.0f, 0.0f);
        __syncthreads();
        if (c >= o) {
            v.x = fmaf(P.x, u.x, fmaf(P.y, u.y, v.x));
            v.y = fmaf(P.z, u.x, fmaf(P.w, u.y, v.y));
        }
        s[c] = v;
        __syncthreads();
    }

    // Initial state of chunk c is the (scanned) end state of chunk c-1.
    float2 ini = (c == 0) ? make_float2(0.0f, 0.0f) : s[c - 1];
    g_init[row * CPR + c] = ini;
}

// ---------------------------------------------------------------------------
// Phase 3: recurrence from true initial state, clip * gain, coalesced output.
__global__ void __launch_bounds__(CPB)
phase3_kernel(const float* __restrict__ x, float* __restrict__ out)
{
    __shared__ float sx[CPB * PAD];
    __shared__ float sy[CPB * PAD];

    const int t  = threadIdx.x;
    const int bg = blockIdx.x * CPB;
    const int g  = bg + t;
    const int row = bg >> 10;
    const int bc  = bg & (CPR - 1);
    const int cir = bc + t;

    const float a1 = g_cf[0], a2 = g_cf[1];
    const float b0 = g_cf[2], b1 = g_cf[3], b2 = g_cf[4];
    const float gn = g_cf[5];

    const float* xr = x + (size_t)row * TLEN;
    const float4* xb4 = (const float4*)(xr + (size_t)bc * CHUNK);
    float4* ob4 = (float4*)(out + (size_t)row * TLEN + (size_t)bc * CHUNK);

    float x1 = 0.0f, x2 = 0.0f;
    if (cir > 0) {
        int n0 = cir * CHUNK;
        x1 = xr[n0 - 1];
        x2 = xr[n0 - 2];
    }

    float2 ini = g_init[g];
    float y1 = ini.x, y2 = ini.y;

    for (int w = 0; w < NW; w++) {
        #pragma unroll
        for (int j = 0; j < 8; j++) {
            int idx = t + CPB * j;
            int c   = idx >> 3;
            int off = idx & 7;
            float4 v = xb4[c * (CHUNK / 4) + w * (WIN / 4) + off];
            float* s = &sx[c * PAD + off * 4];
            s[0] = v.x; s[1] = v.y; s[2] = v.z; s[3] = v.w;
        }
        __syncthreads();

        #pragma unroll
        for (int i = 0; i < WIN; i++) {
            float xn = sx[t * PAD + i];
            float f  = fmaf(b2, x2, fmaf(b1, x1, b0 * xn));
            float y  = fmaf(-a2, y2, fmaf(-a1, y1, f));
            x2 = x1; x1 = xn;
            y2 = y1; y1 = y;
            float yc = fminf(fmaxf(y, -1.0f), 1.0f) * gn;
            sy[t * PAD + i] = yc;
        }
        __syncthreads();

        // Cooperative coalesced store of the output window
        #pragma unroll
        for (int j = 0; j < 8; j++) {
            int idx = t + CPB * j;
            int c   = idx >> 3;
            int off = idx & 7;
            const float* s = &sy[c * PAD + off * 4];
            float4 v;
            v.x = s[0]; v.y = s[1]; v.z = s[2]; v.w = s[3];
            ob4[c * (CHUNK / 4) + w * (WIN / 4) + off] = v;
        }
        // next iteration's __syncthreads() (after the sx refill) orders these
        // sy reads against the next window's sy writes; sx writes don't race
        // because the compute loop above finished reading sx before this point
        // only after a __syncthreads(), and the refill targets sx, not sy.
    }

    g_d[g].x = y1;  // dead store kept out: (not needed) -- intentionally omitted
}

// ---------------------------------------------------------------------------
extern "C" void kernel_launch(void* const* d_in, const int* in_sizes, int n_in,
                              void* d_out, int out_size)
{
    const float* x    = (const float*)d_in[0];
    const float* a    = (const float*)d_in[1];
    const float* b    = (const float*)d_in[2];
    const float* gain = (const float*)d_in[3];
    float* out = (float*)d_out;

    setup_kernel<<<1, 1>>>(a, b, gain);
    phase1_kernel<<<NBLK, CPB>>>(x);
    phase2_kernel<<<BATCH, CPR>>>();
    phase3_kernel<<<NBLK, CPB>>>(x, out);
}

// round 2
// speedup vs baseline: 1.2024x; 1.2024x over previous
#include <cuda_runtime.h>

// ModelFilter: y = gain * clip(IIR2(FIR2(x)), -1, 1)
// Chunked parallel-scan over the order-2 linear recurrence.
//   CHUNK=128, 2048 chunks/row, 131072 chunk-threads total.
//   phase1: zero-IC chunk end states (reads x from DRAM, warms L2)
//   phase2: per-row scan; fp64 matrix powers computed in-block
//   phase3: replay with true initial states (x from L2), clip*gain, stcs out

#define BATCH 64
#define TLEN  262144
#define CHUNK 128
#define CPR   (TLEN / CHUNK)          // 2048 chunks per row
#define TOTAL_CHUNKS (BATCH * CPR)    // 131072
#define CPB   256                     // chunk-threads per block
#define NBLK  (TOTAL_CHUNKS / CPB)    // 512 blocks
#define WIN   16                      // samples staged per window
#define NW    (CHUNK / WIN)           // 8
#define PAD   (WIN + 1)               // 17 -> conflict-free strided reads

__device__ float2 g_d[TOTAL_CHUNKS];     // phase-1 zero-IC end states
__device__ float2 g_init[TOTAL_CHUNKS];  // phase-2 true initial states

// ---------------------------------------------------------------------------
__global__ void __launch_bounds__(CPB, 4)
phase1_kernel(const float* __restrict__ x,
              const float* __restrict__ ac,
              const float* __restrict__ bcf)
{
    __shared__ float sx[CPB * PAD];

    const int t   = threadIdx.x;
    const int bg  = blockIdx.x * CPB;
    const int g   = bg + t;
    const int row = bg >> 11;             // CPB divides CPR
    const int bcc = bg & (CPR - 1);
    const int cir = bcc + t;

    const float a0 = __ldg(&ac[0]);
    const float a1 = __ldg(&ac[1]) / a0, a2 = __ldg(&ac[2]) / a0;
    const float b0 = __ldg(&bcf[0]) / a0, b1 = __ldg(&bcf[1]) / a0,
                b2 = __ldg(&bcf[2]) / a0;

    const float* xr = x + (size_t)row * TLEN;
    const float4* xb4 = (const float4*)(xr + (size_t)bcc * CHUNK);

    float x1 = 0.0f, x2 = 0.0f;
    if (cir > 0) { int n0 = cir * CHUNK; x1 = xr[n0 - 1]; x2 = xr[n0 - 2]; }
    float y1 = 0.0f, y2 = 0.0f;

    for (int w = 0; w < NW; w++) {
        #pragma unroll
        for (int j = 0; j < 4; j++) {          // 4 float4 per thread
            int idx = t + CPB * j;
            int c   = idx >> 2;                // WIN/4 = 4 float4 per chunk-win
            int off = idx & 3;
            float4 v = xb4[c * (CHUNK / 4) + w * (WIN / 4) + off];
            float* s = &sx[c * PAD + off * 4];
            s[0] = v.x; s[1] = v.y; s[2] = v.z; s[3] = v.w;
        }
        __syncthreads();

        #pragma unroll
        for (int i = 0; i < WIN; i++) {
            float xn = sx[t * PAD + i];
            float f  = fmaf(b2, x2, fmaf(b1, x1, b0 * xn));
            float y  = fmaf(-a2, y2, fmaf(-a1, y1, f));
            x2 = x1; x1 = xn;
            y2 = y1; y1 = y;
        }
        __syncthreads();
    }
    g_d[g] = make_float2(y1, y2);
}

// ---------------------------------------------------------------------------
// Phase 2: per-row scan. 1024 threads, 2 chunks/thread (pair-combine with A,
// then 10-level Kogge-Stone with powers of B = A^2).
#define DSQR() { double t00 = m00*m00 + m01*m10, t01 = m00*m01 + m01*m11, \
                        t10 = m10*m00 + m11*m10, t11 = m10*m01 + m11*m11; \
                 m00 = t00; m01 = t01; m10 = t10; m11 = t11; }

__global__ void __launch_bounds__(1024)
phase2_kernel(const float* __restrict__ ac)
{
    __shared__ float2 s[1024];
    __shared__ float4 sA;
    __shared__ float4 sP[10];

    const int t   = threadIdx.x;
    const int row = blockIdx.x;

    if (t == 0) {
        double a0 = (double)ac[0];
        double a1 = (double)ac[1] / a0;
        double a2 = (double)ac[2] / a0;
        double m00 = -a1, m01 = -a2, m10 = 1.0, m11 = 0.0;
        #pragma unroll
        for (int i = 0; i < 7; i++) DSQR()            // A = M^128
        sA = make_float4((float)m00, (float)m01, (float)m10, (float)m11);
        DSQR()                                        // B = A^2
        #pragma unroll
        for (int k = 0; k < 10; k++) {
            sP[k] = make_float4((float)m00, (float)m01, (float)m10, (float)m11);
            DSQR()
        }
    }
    __syncthreads();

    const float4 A = sA;
    float2 d0 = g_d[row * CPR + 2 * t];
    float2 d1 = g_d[row * CPR + 2 * t + 1];
    float2 v;
    v.x = fmaf(A.x, d0.x, fmaf(A.y, d0.y, d1.x));
    v.y = fmaf(A.z, d0.x, fmaf(A.w, d0.y, d1.y));
    s[t] = v;
    __syncthreads();

    #pragma unroll
    for (int k = 0; k < 10; k++) {
        const int o = 1 << k;
        float4 P = sP[k];
        float2 u = (t >= o) ? s[t - o] : make_float2(0.0f, 0.0f);
        __syncthreads();
        if (t >= o) {
            v.x = fmaf(P.x, u.x, fmaf(P.y, u.y, v.x));
            v.y = fmaf(P.z, u.x, fmaf(P.w, u.y, v.y));
        }
        s[t] = v;
        __syncthreads();
    }

    // s[t] = true end state of chunk 2t+1.
    float2 Ep = (t == 0) ? make_float2(0.0f, 0.0f) : s[t - 1];
    float2 i1;   // init of chunk 2t+1 = end of chunk 2t = d0 + A*Ep
    i1.x = fmaf(A.x, Ep.x, fmaf(A.y, Ep.y, d0.x));
    i1.y = fmaf(A.z, Ep.x, fmaf(A.w, Ep.y, d0.y));
    g_init[row * CPR + 2 * t]     = Ep;
    g_init[row * CPR + 2 * t + 1] = i1;
}

// ---------------------------------------------------------------------------
__global__ void __launch_bounds__(CPB, 4)
phase3_kernel(const float* __restrict__ x, float* __restrict__ out,
              const float* __restrict__ ac, const float* __restrict__ bcf,
              const float* __restrict__ gain)
{
    __shared__ float sx[CPB * PAD];
    __shared__ float sy[CPB * PAD];

    const int t   = threadIdx.x;
    const int bg  = blockIdx.x * CPB;
    const int g   = bg + t;
    const int row = bg >> 11;
    const int bcc = bg & (CPR - 1);
    const int cir = bcc + t;

    const float a0 = __ldg(&ac[0]);
    const float a1 = __ldg(&ac[1]) / a0, a2 = __ldg(&ac[2]) / a0;
    const float b0 = __ldg(&bcf[0]) / a0, b1 = __ldg(&bcf[1]) / a0,
                b2 = __ldg(&bcf[2]) / a0;
    const float gn = __ldg(&gain[0]);

    const float* xr = x + (size_t)row * TLEN;
    const float4* xb4 = (const float4*)(xr + (size_t)bcc * CHUNK);
    float4* ob4 = (float4*)(out + (size_t)row * TLEN + (size_t)bcc * CHUNK);

    float x1 = 0.0f, x2 = 0.0f;
    if (cir > 0) { int n0 = cir * CHUNK; x1 = xr[n0 - 1]; x2 = xr[n0 - 2]; }

    float2 ini = __ldg(&g_init[g]);
    float y1 = ini.x, y2 = ini.y;

    for (int w = 0; w < NW; w++) {
        #pragma unroll
        for (int j = 0; j < 4; j++) {
            int idx = t + CPB * j;
            int c   = idx >> 2;
            int off = idx & 3;
            float4 v = xb4[c * (CHUNK / 4) + w * (WIN / 4) + off];
            float* s = &sx[c * PAD + off * 4];
            s[0] = v.x; s[1] = v.y; s[2] = v.z; s[3] = v.w;
        }
        __syncthreads();

        #pragma unroll
        for (int i = 0; i < WIN; i++) {
            float xn = sx[t * PAD + i];
            float f  = fmaf(b2, x2, fmaf(b1, x1, b0 * xn));
            float y  = fmaf(-a2, y2, fmaf(-a1, y1, f));
            x2 = x1; x1 = xn;
            y2 = y1; y1 = y;
            sy[t * PAD + i] = fminf(fmaxf(y, -1.0f), 1.0f) * gn;
        }
        __syncthreads();

        #pragma unroll
        for (int j = 0; j < 4; j++) {
            int idx = t + CPB * j;
            int c   = idx >> 2;
            int off = idx & 3;
            const float* s = &sy[c * PAD + off * 4];
            float4 v;
            v.x = s[0]; v.y = s[1]; v.z = s[2]; v.w = s[3];
            __stcs(&ob4[c * (CHUNK / 4) + w * (WIN / 4) + off], v);
        }
        // The __syncthreads after the next window's sx fill orders these sy
        // reads against the next window's sy writes (sx and sy are disjoint).
    }
}

// ---------------------------------------------------------------------------
extern "C" void kernel_launch(void* const* d_in, const int* in_sizes, int n_in,
                              void* d_out, int out_size)
{
    const float* x    = (const float*)d_in[0];
    const float* a    = (const float*)d_in[1];
    const float* b    = (const float*)d_in[2];
    const float* gain = (const float*)d_in[3];
    float* out = (float*)d_out;

    phase1_kernel<<<NBLK, CPB>>>(x, a, b);
    phase2_kernel<<<BATCH, 1024>>>(a);
    phase3_kernel<<<NBLK, CPB>>>(x, out, a, b, gain);
}

// round 3
// speedup vs baseline: 1.5632x; 1.3001x over previous
#include <cuda_runtime.h>

// ModelFilter: y = gain * clip(IIR2(FIR2(x)), -1, 1)
// Chunked parallel-scan over the order-2 linear recurrence.
//   CHUNK=128, 2048 chunks/row, 131072 chunk-threads total.
//   Inner recurrence uses the step-2 companion form: (y_n, y_{n+1}) from
//   (y_{n-1}, y_{n-2}) -> exposed dependency chain is 1 fma per 2 samples.

#define BATCH 64
#define TLEN  262144
#define CHUNK 128
#define CPR   (TLEN / CHUNK)          // 2048 chunks per row
#define TOTAL_CHUNKS (BATCH * CPR)    // 131072
#define CPB   128                     // chunk-threads per block
#define NBLK  (TOTAL_CHUNKS / CPB)    // 1024 blocks
#define WIN   32                      // samples staged per window
#define NW    (CHUNK / WIN)           // 4
#define PAD   (WIN + 1)               // 33 -> conflict-free strided access

__device__ float2 g_d[TOTAL_CHUNKS];     // phase-1 zero-IC end states
__device__ float2 g_init[TOTAL_CHUNKS];  // phase-2 true initial states

// ---------------------------------------------------------------------------
// Phase 1: zero-IC chunk recurrence -> end states.
__global__ void __launch_bounds__(CPB, 8)
phase1_kernel(const float* __restrict__ x,
              const float* __restrict__ ac,
              const float* __restrict__ bcf)
{
    __shared__ float sx[CPB * PAD];

    const int t   = threadIdx.x;
    const int bg  = blockIdx.x * CPB;
    const int g   = bg + t;
    const int row = bg >> 11;             // CPB divides CPR
    const int bcc = bg & (CPR - 1);
    const int cir = bcc + t;

    const float a0 = __ldg(&ac[0]);
    const float a1 = __ldg(&ac[1]) / a0, a2 = __ldg(&ac[2]) / a0;
    const float b0 = __ldg(&bcf[0]) / a0, b1 = __ldg(&bcf[1]) / a0,
                b2 = __ldg(&bcf[2]) / a0;
    const float na1 = -a1, na2 = -a2;
    const float c00 = fmaf(a1, a1, -a2);   // a1^2 - a2
    const float c01 = a1 * a2;

    const float* xr = x + (size_t)row * TLEN;
    const float4* xb4 = (const float4*)(xr + (size_t)bcc * CHUNK);

    float x1 = 0.0f, x2 = 0.0f;
    if (cir > 0) { int n0 = cir * CHUNK; x1 = xr[n0 - 1]; x2 = xr[n0 - 2]; }
    float y1 = 0.0f, y2 = 0.0f;           // y[n-1], y[n-2]

    for (int w = 0; w < NW; w++) {
        #pragma unroll
        for (int j = 0; j < 8; j++) {          // CPB*WIN/4 = CPB*8 float4
            int idx = t + CPB * j;
            int c   = idx >> 3;                // WIN/4 = 8 float4 per chunk-win
            int off = idx & 7;
            float4 v = xb4[c * (CHUNK / 4) + w * (WIN / 4) + off];
            float* s = &sx[c * PAD + off * 4];
            s[0] = v.x; s[1] = v.y; s[2] = v.z; s[3] = v.w;
        }
        __syncthreads();

        #pragma unroll
        for (int i = 0; i < WIN; i += 2) {
            float xn0 = sx[t * PAD + i];
            float xn1 = sx[t * PAD + i + 1];
            float f0 = fmaf(b2, x2, fmaf(b1, x1, b0 * xn0));
            float f1 = fmaf(b2, x1, fmaf(b1, xn0, b0 * xn1));
            float F1 = fmaf(na1, f0, f1);
            float t0 = fmaf(na2, y2, f0);       // slack: y2 is 2 samples old
            float t1 = fmaf(c01, y2, F1);
            float yA = fmaf(na1, y1, t0);       // y_n
            float yB = fmaf(c00, y1, t1);       // y_{n+1}  (critical edge)
            y2 = yA; y1 = yB;
            x2 = xn0; x1 = xn1;
        }
        __syncthreads();
    }
    g_d[g] = make_float2(y1, y2);
}

// ---------------------------------------------------------------------------
// Phase 2: per-row scan. 1024 threads, 2 chunks/thread (pair-combine with A,
// then 10-level Kogge-Stone with powers of B = A^2). fp64 matrix powers.
#define DSQR() { double t00 = m00*m00 + m01*m10, t01 = m00*m01 + m01*m11, \
                        t10 = m10*m00 + m11*m10, t11 = m10*m01 + m11*m11; \
                 m00 = t00; m01 = t01; m10 = t10; m11 = t11; }

__global__ void __launch_bounds__(1024)
phase2_kernel(const float* __restrict__ ac)
{
    __shared__ float2 s[1024];
    __shared__ float4 sA;
    __shared__ float4 sP[10];

    const int t   = threadIdx.x;
    const int row = blockIdx.x;

    if (t == 0) {
        double a0 = (double)ac[0];
        double a1 = (double)ac[1] / a0;
        double a2 = (double)ac[2] / a0;
        double m00 = -a1, m01 = -a2, m10 = 1.0, m11 = 0.0;
        #pragma unroll
        for (int i = 0; i < 7; i++) DSQR()            // A = M^128
        sA = make_float4((float)m00, (float)m01, (float)m10, (float)m11);
        DSQR()                                        // B = A^2
        #pragma unroll
        for (int k = 0; k < 10; k++) {
            sP[k] = make_float4((float)m00, (float)m01, (float)m10, (float)m11);
            DSQR()
        }
    }
    __syncthreads();

    const float4 A = sA;
    float2 d0 = g_d[row * CPR + 2 * t];
    float2 d1 = g_d[row * CPR + 2 * t + 1];
    float2 v;
    v.x = fmaf(A.x, d0.x, fmaf(A.y, d0.y, d1.x));
    v.y = fmaf(A.z, d0.x, fmaf(A.w, d0.y, d1.y));
    s[t] = v;
    __syncthreads();

    #pragma unroll
    for (int k = 0; k < 10; k++) {
        const int o = 1 << k;
        float4 P = sP[k];
        float2 u = (t >= o) ? s[t - o] : make_float2(0.0f, 0.0f);
        __syncthreads();
        if (t >= o) {
            v.x = fmaf(P.x, u.x, fmaf(P.y, u.y, v.x));
            v.y = fmaf(P.z, u.x, fmaf(P.w, u.y, v.y));
        }
        s[t] = v;
        __syncthreads();
    }

    // s[t] = true end state of chunk 2t+1.
    float2 Ep = (t == 0) ? make_float2(0.0f, 0.0f) : s[t - 1];
    float2 i1;   // init of chunk 2t+1 = end of chunk 2t = d0 + A*Ep
    i1.x = fmaf(A.x, Ep.x, fmaf(A.y, Ep.y, d0.x));
    i1.y = fmaf(A.z, Ep.x, fmaf(A.w, Ep.y, d0.y));
    g_init[row * CPR + 2 * t]     = Ep;
    g_init[row * CPR + 2 * t + 1] = i1;
}

// ---------------------------------------------------------------------------
// Phase 3: replay from true initial state, clip*gain, in-place smem staging.
__global__ void __launch_bounds__(CPB, 8)
phase3_kernel(const float* __restrict__ x, float* __restrict__ out,
              const float* __restrict__ ac, const float* __restrict__ bcf,
              const float* __restrict__ gain)
{
    __shared__ float sx[CPB * PAD];

    const int t   = threadIdx.x;
    const int bg  = blockIdx.x * CPB;
    const int g   = bg + t;
    const int row = bg >> 11;
    const int bcc = bg & (CPR - 1);
    const int cir = bcc + t;

    const float a0 = __ldg(&ac[0]);
    const float a1 = __ldg(&ac[1]) / a0, a2 = __ldg(&ac[2]) / a0;
    const float b0 = __ldg(&bcf[0]) / a0, b1 = __ldg(&bcf[1]) / a0,
                b2 = __ldg(&bcf[2]) / a0;
    const float na1 = -a1, na2 = -a2;
    const float c00 = fmaf(a1, a1, -a2);
    const float c01 = a1 * a2;
    const float gn = __ldg(&gain[0]);

    const float* xr = x + (size_t)row * TLEN;
    const float4* xb4 = (const float4*)(xr + (size_t)bcc * CHUNK);
    float4* ob4 = (float4*)(out + (size_t)row * TLEN + (size_t)bcc * CHUNK);

    float x1 = 0.0f, x2 = 0.0f;
    if (cir > 0) { int n0 = cir * CHUNK; x1 = __ldcs(&xr[n0 - 1]); x2 = __ldcs(&xr[n0 - 2]); }

    float2 ini = __ldg(&g_init[g]);
    float y1 = ini.x, y2 = ini.y;

    for (int w = 0; w < NW; w++) {
        #pragma unroll
        for (int j = 0; j < 8; j++) {
            int idx = t + CPB * j;
            int c   = idx >> 3;
            int off = idx & 7;
            float4 v = __ldcs(&xb4[c * (CHUNK / 4) + w * (WIN / 4) + off]);
            float* s = &sx[c * PAD + off * 4];
            s[0] = v.x; s[1] = v.y; s[2] = v.z; s[3] = v.w;
        }
        __syncthreads();

        // Compute and overwrite own smem row with clipped output (in place:
        // each thread reads/writes only row t).
        #pragma unroll
        for (int i = 0; i < WIN; i += 2) {
            float xn0 = sx[t * PAD + i];
            float xn1 = sx[t * PAD + i + 1];
            float f0 = fmaf(b2, x2, fmaf(b1, x1, b0 * xn0));
            float f1 = fmaf(b2, x1, fmaf(b1, xn0, b0 * xn1));
            float F1 = fmaf(na1, f0, f1);
            float t0 = fmaf(na2, y2, f0);
            float t1 = fmaf(c01, y2, F1);
            float yA = fmaf(na1, y1, t0);
            float yB = fmaf(c00, y1, t1);
            y2 = yA; y1 = yB;
            x2 = xn0; x1 = xn1;
            sx[t * PAD + i]     = fminf(fmaxf(yA, -1.0f), 1.0f) * gn;
            sx[t * PAD + i + 1] = fminf(fmaxf(yB, -1.0f), 1.0f) * gn;
        }
        __syncthreads();

        #pragma unroll
        for (int j = 0; j < 8; j++) {
            int idx = t + CPB * j;
            int c   = idx >> 3;
            int off = idx & 7;
            const float* s = &sx[c * PAD + off * 4];
            float4 v;
            v.x = s[0]; v.y = s[1]; v.z = s[2]; v.w = s[3];
            __stcs(&ob4[c * (CHUNK / 4) + w * (WIN / 4) + off], v);
        }
        __syncthreads();   // next window's load overwrites rows being read
    }
}

// ---------------------------------------------------------------------------
extern "C" void kernel_launch(void* const* d_in, const int* in_sizes, int n_in,
                              void* d_out, int out_size)
{
    const float* x    = (const float*)d_in[0];
    const float* a    = (const float*)d_in[1];
    const float* b    = (const float*)d_in[2];
    const float* gain = (const float*)d_in[3];
    float* out = (float*)d_out;

    phase1_kernel<<<NBLK, CPB>>>(x, a, b);
    phase2_kernel<<<BATCH, 1024>>>(a);
    phase3_kernel<<<NBLK, CPB>>>(x, out, a, b, gain);
}